// round 2
// baseline (speedup 1.0000x reference)
#include <cuda_runtime.h>
#include <math.h>

#define HH 128
#define WWD 128
#define HWP (HH*WWD)
#define CIN 64
#define COUT 64
#define BB 2
#define TPX 32

// ---------------- device scratch (allowed: __device__ globals) ----------------
__device__ float g_nhwc[BB*HWP*CIN];   // 8 MB, input in NHWC
__device__ float g_pooled[BB*CIN];     // per (b,c) plane sums
__device__ float g_Mg[8*81];           // 8 tap-transform matrices (9x9)

// Mbase: base[k] = sum_{k'} Mbase[k][k'] * wr[k'],  S = sqrt(2)/2
// S^2 = 0.5, SM = S(1-S), M2 = (1-S)^2
#define SMV 0.20710678118654746f
#define M2V 0.08578643762690495f
__device__ const float c_Mbase[81] = {
    0.5f, SMV , 0.f , SMV , M2V , 0.f , 0.f , 0.f , 0.f ,
    0.f , 1.f , 0.f , 0.f , 0.f , 0.f , 0.f , 0.f , 0.f ,
    0.f , SMV , 0.5f, 0.f , M2V , SMV , 0.f , 0.f , 0.f ,
    0.f , 0.f , 0.f , 1.f , 0.f , 0.f , 0.f , 0.f , 0.f ,
    0.f , 0.f , 0.f , 0.f , 1.f , 0.f , 0.f , 0.f , 0.f ,
    0.f , 0.f , 0.f , 0.f , 0.f , 1.f , 0.f , 0.f , 0.f ,
    0.f , 0.f , 0.f , SMV , M2V , 0.f , 0.5f, SMV , 0.f ,
    0.f , 0.f , 0.f , 0.f , 0.f , 0.f , 0.f , 1.f , 0.f ,
    0.f , 0.f , 0.f , 0.f , M2V , SMV , 0.f , SMV , 0.5f
};

__device__ const int c_P[8][9] = {
    {0,1,2,3,4,5,6,7,8},
    {3,0,1,6,4,2,7,8,5},
    {6,3,0,7,4,1,8,5,2},
    {7,6,3,8,4,0,5,2,1},
    {8,7,6,5,4,3,2,1,0},
    {5,8,7,2,4,6,1,0,3},
    {2,5,8,1,4,7,0,3,6},
    {1,2,5,0,4,8,3,6,7}
};

// ---------------- kernel 1: NCHW -> NHWC transpose ----------------
__global__ __launch_bounds__(256) void nhwc_kernel(const float* __restrict__ in) {
    __shared__ float tile[64][33];
    int bid = blockIdx.x;              // 1024 blocks: b(2) * y(128) * xt(4)
    int b   = bid >> 9;
    int rem = bid & 511;
    int y   = rem >> 2;
    int x0  = (rem & 3) << 5;
    int t   = threadIdx.x;

    int xl = t & 31, cb = t >> 5;      // load: lanes over x -> coalesced
    #pragma unroll
    for (int i = 0; i < 8; i++) {
        int c = cb + i*8;
        tile[c][xl] = in[(((b*64 + c)*128 + y)*128) + x0 + xl];
    }
    __syncthreads();
    int c2 = t & 63, xb = t >> 6;      // store: lanes over c -> coalesced
    #pragma unroll
    for (int i = 0; i < 8; i++) {
        int x = xb + i*4;
        g_nhwc[(((b*128 + y)*128) + x0 + x)*64 + c2] = tile[c2][x];
    }
}

// ---------------- kernel 2: per-(b,c) plane sums ----------------
__global__ __launch_bounds__(256) void pool_kernel(const float* __restrict__ in) {
    __shared__ float red[8];
    int bc = blockIdx.x, t = threadIdx.x;
    const float* p = in + (size_t)bc * HWP;
    float s = 0.f;
    for (int i = t; i < HWP; i += 256) s += p[i];
    #pragma unroll
    for (int o = 16; o > 0; o >>= 1) s += __shfl_down_sync(0xffffffffu, s, o);
    if ((t & 31) == 0) red[t >> 5] = s;
    __syncthreads();
    if (t == 0) {
        float tot = 0.f;
        #pragma unroll
        for (int i = 0; i < 8; i++) tot += red[i];
        g_pooled[bc] = tot;
    }
}

// ---------------- kernel 3: r = sigmoid(fc), build M_g ----------------
__global__ __launch_bounds__(256) void setup_kernel(const float* __restrict__ fc_w,
                                                    const float* __restrict__ fc_b) {
    __shared__ float r_s[4];
    int t = threadIdx.x;
    if (t < 4) {
        float z = fc_b[t];
        const float inv = 1.f / (float)HWP;
        for (int c = 0; c < 64; c++) {
            float psum = (g_pooled[c] + g_pooled[64 + c]) * inv;
            z += psum * fc_w[t*64 + c];
        }
        r_s[t] = 1.f / (1.f + expf(-z));
    }
    __syncthreads();
    for (int e = t; e < 648; e += 256) {
        int g = e / 81, kk = e % 81;
        int k = kk / 9, k2 = kk % 9;
        int pk = c_P[g][k];
        float mb = c_Mbase[pk*9 + k2];
        float v;
        if ((g & 1) == 0) {
            float rr = r_s[g >> 1];
            v = rr * mb + (1.f - rr) * ((k2 == pk) ? 1.f : 0.f);
        } else {
            v = mb;
        }
        g_Mg[e] = v;
    }
}

// ---------------- kernel 4: fused DCN (sample + tap-transform + 64x576 GEMM) ----------------
// dynamic smem layout (floats):
//   [0 .. 2592)      A_s[p][81]              (phase0/1)   -- aliased by Ws[64][64] in phase2
//   [2592 .. 3744)   idx_s[p][9][4] (ints)   (phase0/1)
//   [3744 .. 4896)   wgt_s[p][9][4]          (phase0/1)
//   [4896 .. 5152)   wc8_s[p][8]
//   [5152 .. 24736)  u_s[576][34]
// total 24736 floats = 98944 bytes
#define SMEM_FLOATS 24736
#define SMEM_BYTES  (SMEM_FLOATS*4)

__global__ __launch_bounds__(256) void main_kernel(
    const float* __restrict__ offset, const float* __restrict__ mask,
    const float* __restrict__ wc8g,   const float* __restrict__ weight,
    const float* __restrict__ bias,   float* __restrict__ out)
{
    extern __shared__ float sm[];
    float* A_s   = sm;                    // [32][81]
    int*   idx_s = (int*)(sm + 2592);     // [32*9][4]
    float* wgt_s = sm + 3744;             // [32*9][4]
    float* Ws    = sm;                    // phase2 alias: [64][64]
    float* wc8_s = sm + 4896;             // [32][8]
    float* u_s   = sm + 5152;             // [576][34]

    int t    = threadIdx.x;
    int bid  = blockIdx.x;                // 1024 blocks: b(2) * 512 tiles
    int b    = bid >> 9;
    int tbase = (bid & 511) << 5;         // 32 aligned -> single h row
    int h    = tbase >> 7;
    int w0   = tbase & 127;

    // ---- phase 0a: load wc8 (coalesced: lanes over pixels) ----
    {
        int g = t >> 5, p = t & 31;
        wc8_s[p*8 + g] = wc8g[(((b*8 + g) << 14)) + tbase + p];
    }

    // ---- phase 0b: per-(pixel,tap) bilinear indices & weights (mask folded in) ----
    for (int task = t; task < 288; task += 256) {
        int p = task & 31, k = task >> 5;
        int pix = tbase + p;
        float offy = offset[((b*18 + 2*k    ) << 14) + pix];
        float offx = offset[((b*18 + 2*k + 1) << 14) + pix];
        float mval = mask  [((b*9  + k      ) << 14) + pix];
        float py = (float)h        + (float)(k/3) - 1.f + offy;
        float px = (float)(w0 + p) + (float)(k%3) - 1.f + offx;
        float y0f = floorf(py), x0f = floorf(px);
        float ly = py - y0f, lx = px - x0f;
        int y0 = (int)y0f, x0i = (int)x0f;
        int y1 = y0 + 1, x1 = x0i + 1;
        bool vy0 = (y0 >= 0) & (y0 <= 127);
        bool vy1 = (y1 >= 0) & (y1 <= 127);
        bool vx0 = (x0i >= 0) & (x0i <= 127);
        bool vx1 = (x1 >= 0) & (x1 <= 127);
        float w00 = (1.f-ly)*(1.f-lx) * ((vy0 & vx0) ? mval : 0.f);
        float w01 = (1.f-ly)*lx       * ((vy0 & vx1) ? mval : 0.f);
        float w10 = ly*(1.f-lx)       * ((vy1 & vx0) ? mval : 0.f);
        float w11 = ly*lx             * ((vy1 & vx1) ? mval : 0.f);
        int cy0 = min(max(y0, 0), 127), cy1 = min(max(y1, 0), 127);
        int cx0 = min(max(x0i,0), 127), cx1 = min(max(x1, 0), 127);
        int b4 = (p*9 + k)*4;
        idx_s[b4+0] = cy0*128 + cx0;
        idx_s[b4+1] = cy0*128 + cx1;
        idx_s[b4+2] = cy1*128 + cx0;
        idx_s[b4+3] = cy1*128 + cx1;
        wgt_s[b4+0] = w00; wgt_s[b4+1] = w01; wgt_s[b4+2] = w10; wgt_s[b4+3] = w11;
    }
    __syncthreads();

    // ---- phase 0c: per-pixel 9x9 matrix A = sum_g wc8[g] * M_g ----
    for (int e = t; e < 2592; e += 256) {
        int p = e & 31, kk = e >> 5;  // kk in [0,81)
        float a = 0.f;
        #pragma unroll
        for (int g = 0; g < 8; g++) a += wc8_s[p*8 + g] * g_Mg[g*81 + kk];
        A_s[p*81 + kk] = a;
    }
    __syncthreads();

    // ---- phase 1: gather + bilinear + tap transform -> u_s[c*9+k'][p] ----
    {
        const float* inb = g_nhwc + ((size_t)b << 20);  // b * 16384 * 64
        int warp = t >> 5, lane = t & 31;
        for (int pp = 0; pp < 4; pp++) {
            int p = warp*4 + pp;
            float ua[9], ub[9];
            #pragma unroll
            for (int i = 0; i < 9; i++) { ua[i] = 0.f; ub[i] = 0.f; }
            #pragma unroll
            for (int k = 0; k < 9; k++) {
                int4   id = ((const int4*)  idx_s)[p*9 + k];
                float4 wg = ((const float4*)wgt_s)[p*9 + k];
                float va = wg.x * inb[id.x*64 + lane]
                         + wg.y * inb[id.y*64 + lane]
                         + wg.z * inb[id.z*64 + lane]
                         + wg.w * inb[id.w*64 + lane];
                float vb = wg.x * inb[id.x*64 + 32 + lane]
                         + wg.y * inb[id.y*64 + 32 + lane]
                         + wg.z * inb[id.z*64 + 32 + lane]
                         + wg.w * inb[id.w*64 + 32 + lane];
                const float* Ap = A_s + p*81 + k*9;
                #pragma unroll
                for (int k2 = 0; k2 < 9; k2++) {
                    float a = Ap[k2];
                    ua[k2] += a * va;
                    ub[k2] += a * vb;
                }
            }
            #pragma unroll
            for (int k2 = 0; k2 < 9; k2++) {
                u_s[((lane     )*9 + k2)*34 + p] = ua[k2];
                u_s[((lane + 32)*9 + k2)*34 + p] = ub[k2];
            }
        }
    }

    // ---- phase 2: GEMM out[64 x 32] = weight[64 x 576] * u[576 x 32] ----
    int po = t & 15;          // pixel pair index -> pixels 2po, 2po+1
    int o4 = (t >> 4) << 2;   // 4 consecutive output rows
    float acc[4][2];
    #pragma unroll
    for (int j = 0; j < 4; j++) { acc[j][0] = 0.f; acc[j][1] = 0.f; }

    for (int ch = 0; ch < 9; ch++) {
        __syncthreads();   // prev chunk compute done / phase0-1 smem free to alias
        #pragma unroll
        for (int r = 0; r < 16; r++) {
            int lin = r*256 + t;
            int o = lin >> 6, kk = lin & 63;
            Ws[o*64 + kk] = weight[o*576 + ch*64 + kk];
        }
        __syncthreads();
        const float* ub = u_s + ch*64*34 + 2*po;
        #pragma unroll 4
        for (int kk = 0; kk < 64; kk++) {
            float2 uv = *(const float2*)(ub + kk*34);
            #pragma unroll
            for (int j = 0; j < 4; j++) {
                float wv = Ws[(o4 + j)*64 + kk];
                acc[j][0] += wv * uv.x;
                acc[j][1] += wv * uv.y;
            }
        }
    }

    // ---- epilogue: + sum_g wc8[g]*bias[g*64+o], write NCHW out ----
    #pragma unroll
    for (int j = 0; j < 4; j++) {
        int o = o4 + j;
        #pragma unroll
        for (int pp = 0; pp < 2; pp++) {
            int p = 2*po + pp;
            float be = 0.f;
            #pragma unroll
            for (int g = 0; g < 8; g++) be += wc8_s[p*8 + g] * bias[g*64 + o];
            out[(((b << 6) + o) << 14) + tbase + p] = acc[j][pp] + be;
        }
    }
}

// ---------------- launch ----------------
extern "C" void kernel_launch(void* const* d_in, const int* in_sizes, int n_in,
                              void* d_out, int out_size) {
    const float* input  = (const float*)d_in[0];
    const float* offset = (const float*)d_in[1];
    const float* maskp  = (const float*)d_in[2];
    const float* w_c8   = (const float*)d_in[3];
    const float* weight = (const float*)d_in[4];
    const float* bias   = (const float*)d_in[5];
    const float* fc_w   = (const float*)d_in[6];
    const float* fc_b   = (const float*)d_in[7];
    float* out = (float*)d_out;

    cudaFuncSetAttribute(main_kernel, cudaFuncAttributeMaxDynamicSharedMemorySize, SMEM_BYTES);

    nhwc_kernel <<<1024, 256>>>(input);
    pool_kernel <<<128, 256>>>(input);
    setup_kernel<<<1, 256>>>(fc_w, fc_b);
    main_kernel <<<1024, 256, SMEM_BYTES>>>(offset, maskp, w_c8, weight, bias, out);
}

// round 3
// speedup vs baseline: 1.0217x; 1.0217x over previous
#include <cuda_runtime.h>
#include <math.h>

#define HH 128
#define WWD 128
#define HWP (HH*WWD)
#define BB 2

// ---------------- device scratch ----------------
__device__ float g_nhwc[BB*HWP*64];    // 8 MB, input in NHWC
__device__ float g_pooled[BB*64];      // per (b,c) plane sums
__device__ float g_Mg[8*81];           // 8 tap-transform matrices (9x9)
__device__ float g_wt[576*64];         // weight transposed+permuted: [pos][o]

#define SMV 0.20710678118654746f
#define M2V 0.08578643762690495f
__device__ const float c_Mbase[81] = {
    0.5f, SMV , 0.f , SMV , M2V , 0.f , 0.f , 0.f , 0.f ,
    0.f , 1.f , 0.f , 0.f , 0.f , 0.f , 0.f , 0.f , 0.f ,
    0.f , SMV , 0.5f, 0.f , M2V , SMV , 0.f , 0.f , 0.f ,
    0.f , 0.f , 0.f , 1.f , 0.f , 0.f , 0.f , 0.f , 0.f ,
    0.f , 0.f , 0.f , 0.f , 1.f , 0.f , 0.f , 0.f , 0.f ,
    0.f , 0.f , 0.f , 0.f , 0.f , 1.f , 0.f , 0.f , 0.f ,
    0.f , 0.f , 0.f , SMV , M2V , 0.f , 0.5f, SMV , 0.f ,
    0.f , 0.f , 0.f , 0.f , 0.f , 0.f , 0.f , 1.f , 0.f ,
    0.f , 0.f , 0.f , 0.f , M2V , SMV , 0.f , SMV , 0.5f
};

__device__ const int c_P[8][9] = {
    {0,1,2,3,4,5,6,7,8},
    {3,0,1,6,4,2,7,8,5},
    {6,3,0,7,4,1,8,5,2},
    {7,6,3,8,4,0,5,2,1},
    {8,7,6,5,4,3,2,1,0},
    {5,8,7,2,4,6,1,0,3},
    {2,5,8,1,4,7,0,3,6},
    {1,2,5,0,4,8,3,6,7}
};

// ---------------- kernel 1: NCHW -> NHWC transpose ----------------
__global__ __launch_bounds__(256) void nhwc_kernel(const float* __restrict__ in) {
    __shared__ float tile[64][33];
    int bid = blockIdx.x;
    int b   = bid >> 9;
    int rem = bid & 511;
    int y   = rem >> 2;
    int x0  = (rem & 3) << 5;
    int t   = threadIdx.x;

    int xl = t & 31, cb = t >> 5;
    #pragma unroll
    for (int i = 0; i < 8; i++) {
        int c = cb + i*8;
        tile[c][xl] = in[(((b*64 + c)*128 + y)*128) + x0 + xl];
    }
    __syncthreads();
    int c2 = t & 63, xb = t >> 6;
    #pragma unroll
    for (int i = 0; i < 8; i++) {
        int x = xb + i*4;
        g_nhwc[(((b*128 + y)*128) + x0 + x)*64 + c2] = tile[c2][x];
    }
}

// ---------------- kernel 1b: weight transpose + k-order permutation ----------------
// stored k-position pos = (c>>1)*18 + k2*2 + (c&1)  (channel-pair interleaved)
__global__ __launch_bounds__(256) void wt_kernel(const float* __restrict__ w) {
    int e = blockIdx.x*256 + threadIdx.x;   // 36864 = 64 o * 576
    if (e < 64*576) {
        int o = e / 576, j = e - o*576;     // j = c*9 + k2  (coalesced read)
        int c = j / 9, k2 = j - c*9;
        int pos = (c >> 1)*18 + k2*2 + (c & 1);
        g_wt[pos*64 + o] = w[e];
    }
}

// ---------------- kernel 2: per-(b,c) plane sums ----------------
__global__ __launch_bounds__(256) void pool_kernel(const float* __restrict__ in) {
    __shared__ float red[8];
    int bc = blockIdx.x, t = threadIdx.x;
    const float* p = in + (size_t)bc * HWP;
    float s = 0.f;
    for (int i = t; i < HWP; i += 256) s += p[i];
    #pragma unroll
    for (int o = 16; o > 0; o >>= 1) s += __shfl_down_sync(0xffffffffu, s, o);
    if ((t & 31) == 0) red[t >> 5] = s;
    __syncthreads();
    if (t == 0) {
        float tot = 0.f;
        #pragma unroll
        for (int i = 0; i < 8; i++) tot += red[i];
        g_pooled[bc] = tot;
    }
}

// ---------------- kernel 3: r = sigmoid(fc), build M_g ----------------
__global__ __launch_bounds__(256) void setup_kernel(const float* __restrict__ fc_w,
                                                    const float* __restrict__ fc_b) {
    __shared__ float r_s[4];
    int t = threadIdx.x;
    if (t < 4) {
        float z = fc_b[t];
        const float inv = 1.f / (float)HWP;
        for (int c = 0; c < 64; c++) {
            float psum = (g_pooled[c] + g_pooled[64 + c]) * inv;
            z += psum * fc_w[t*64 + c];
        }
        r_s[t] = 1.f / (1.f + expf(-z));
    }
    __syncthreads();
    for (int e = t; e < 648; e += 256) {
        int g = e / 81, kk = e % 81;
        int k = kk / 9, k2 = kk % 9;
        int pk = c_P[g][k];
        float mb = c_Mbase[pk*9 + k2];
        float v;
        if ((g & 1) == 0) {
            float rr = r_s[g >> 1];
            v = rr * mb + (1.f - rr) * ((k2 == pk) ? 1.f : 0.f);
        } else {
            v = mb;
        }
        g_Mg[e] = v;
    }
}

// ---------------- kernel 4: fused DCN ----------------
// smem layout (floats):
//   [0 .. 3584)       A_s[32 px][9 k][12 pad]       (phase0/1)  -- aliased by Ws[64][66] (4224) in phase2
//   [3584 .. 4736)    idx_s[32][9][4] ints          (phase0/1)      and by outbuf[64][33] (2112) in epilogue
//   [4736 .. 5888)    wgt_s[32][9][4]
//   [5888 .. 6144)    wc8_s[32][8]                  (whole kernel)
//   [6144 .. 24576)   u_s[32 px][576]               (permuted k-order)
#define SMEM_FLOATS 24576
#define SMEM_BYTES  (SMEM_FLOATS*4)

__global__ __launch_bounds__(256) void main_kernel(
    const float* __restrict__ offset, const float* __restrict__ mask,
    const float* __restrict__ wc8g,   const float* __restrict__ bias,
    float* __restrict__ out)
{
    extern __shared__ float sm[];
    float* A_s   = sm;                    // [32][9][12]
    int*   idx_s = (int*)(sm + 3584);     // [32*9][4]
    float* wgt_s = sm + 4736;             // [32*9][4]
    float* wc8_s = sm + 5888;             // [32][8]
    float* u_s   = sm + 6144;             // [32][576]
    float* Ws    = sm;                    // phase2 alias: [64 kk][66]
    float* outb  = sm;                    // epilogue alias: [64 o][33]

    int t     = threadIdx.x;
    int bid   = blockIdx.x;               // 1024: b(2) * 512 tiles
    int b     = bid >> 9;
    int tbase = (bid & 511) << 5;
    int h     = tbase >> 7;
    int w0    = tbase & 127;
    int w     = t >> 5;                   // warp id (= pixel group / 4)
    int l     = t & 31;                   // lane

    // ---- phase 0a: wc8 ----
    wc8_s[(t & 31)*8 + (t >> 5)] = wc8g[((b*8 + (t >> 5)) << 14) + tbase + (t & 31)];

    // ---- phase 0b: bilinear indices & weights (mask folded) ----
    for (int task = t; task < 288; task += 256) {
        int p = task & 31, k = task >> 5;
        int pix = tbase + p;
        float offy = offset[((b*18 + 2*k    ) << 14) + pix];
        float offx = offset[((b*18 + 2*k + 1) << 14) + pix];
        float mval = mask  [((b*9  + k      ) << 14) + pix];
        float py = (float)h        + (float)(k/3) - 1.f + offy;
        float px = (float)(w0 + p) + (float)(k%3) - 1.f + offx;
        float y0f = floorf(py), x0f = floorf(px);
        float ly = py - y0f, lx = px - x0f;
        int y0 = (int)y0f, x0i = (int)x0f;
        int y1 = y0 + 1, x1 = x0i + 1;
        bool vy0 = (y0 >= 0) & (y0 <= 127);
        bool vy1 = (y1 >= 0) & (y1 <= 127);
        bool vx0 = (x0i >= 0) & (x0i <= 127);
        bool vx1 = (x1 >= 0) & (x1 <= 127);
        float w00 = (1.f-ly)*(1.f-lx) * ((vy0 & vx0) ? mval : 0.f);
        float w01 = (1.f-ly)*lx       * ((vy0 & vx1) ? mval : 0.f);
        float w10 = ly*(1.f-lx)       * ((vy1 & vx0) ? mval : 0.f);
        float w11 = ly*lx             * ((vy1 & vx1) ? mval : 0.f);
        int cy0 = min(max(y0, 0), 127), cy1 = min(max(y1, 0), 127);
        int cx0 = min(max(x0i,0), 127), cx1 = min(max(x1, 0), 127);
        int b4 = (p*9 + k)*4;
        idx_s[b4+0] = cy0*128 + cx0;
        idx_s[b4+1] = cy0*128 + cx1;
        idx_s[b4+2] = cy1*128 + cx0;
        idx_s[b4+3] = cy1*128 + cx1;
        wgt_s[b4+0] = w00; wgt_s[b4+1] = w01; wgt_s[b4+2] = w10; wgt_s[b4+3] = w11;
    }
    __syncthreads();

    // ---- phase 0c: A[p][k][k2] = sum_g wc8[g] * M_g  (padded rows of 12) ----
    for (int e = t; e < 2592; e += 256) {
        int p = e & 31, kk = e >> 5;          // kk in [0,81)
        int k = kk / 9, k2 = kk - k*9;
        float a = 0.f;
        #pragma unroll
        for (int g = 0; g < 8; g++) a += wc8_s[p*8 + g] * g_Mg[g*81 + kk];
        A_s[p*112 + k*12 + k2] = a;
    }
    __syncthreads();

    // ---- phase 1: gather + bilinear + tap transform -> u_s[p][pos] ----
    {
        const float2* ib = (const float2*)(g_nhwc + ((size_t)b << 20));
        const int4*   idx4 = (const int4*)idx_s;
        const float4* wgt4 = (const float4*)wgt_s;
        #pragma unroll
        for (int pp = 0; pp < 4; pp++) {
            int p = w*4 + pp;
            float2 ua[9];
            #pragma unroll
            for (int i = 0; i < 9; i++) { ua[i].x = 0.f; ua[i].y = 0.f; }
            #pragma unroll
            for (int k = 0; k < 9; k++) {
                int4   id = idx4[p*9 + k];
                float4 wg = wgt4[p*9 + k];
                float2 c00 = ib[id.x*32 + l];
                float2 c01 = ib[id.y*32 + l];
                float2 c10 = ib[id.z*32 + l];
                float2 c11 = ib[id.w*32 + l];
                float vx = wg.x*c00.x + wg.y*c01.x + wg.z*c10.x + wg.w*c11.x;
                float vy = wg.x*c00.y + wg.y*c01.y + wg.z*c10.y + wg.w*c11.y;
                const float* Ab = A_s + p*112 + k*12;
                float4 a0 = *(const float4*)(Ab);
                float4 a1 = *(const float4*)(Ab + 4);
                float  a8 = Ab[8];
                ua[0].x += a0.x*vx; ua[0].y += a0.x*vy;
                ua[1].x += a0.y*vx; ua[1].y += a0.y*vy;
                ua[2].x += a0.z*vx; ua[2].y += a0.z*vy;
                ua[3].x += a0.w*vx; ua[3].y += a0.w*vy;
                ua[4].x += a1.x*vx; ua[4].y += a1.x*vy;
                ua[5].x += a1.y*vx; ua[5].y += a1.y*vy;
                ua[6].x += a1.z*vx; ua[6].y += a1.z*vy;
                ua[7].x += a1.w*vx; ua[7].y += a1.w*vy;
                ua[8].x += a8  *vx; ua[8].y += a8  *vy;
            }
            float2* urow = (float2*)(u_s + p*576);
            #pragma unroll
            for (int k2 = 0; k2 < 9; k2++) urow[l*9 + k2] = ua[k2];
        }
    }

    // ---- phase 2: GEMM out[64 o x 32 px] = Wt[576 x 64]^T * u[32 px][576] ----
    // warp w owns pixels 4w..4w+3; lane l owns outputs 2l, 2l+1
    float acc[8];   // [j 2o][i 4px]
    #pragma unroll
    for (int i = 0; i < 8; i++) acc[i] = 0.f;

    for (int ch = 0; ch < 9; ch++) {
        __syncthreads();   // previous chunk consumed / phase0-1 scratch dead
        {
            int o = t & 63, kq = t >> 6;
            #pragma unroll
            for (int r = 0; r < 16; r++) {
                int kk = r*4 + kq;
                Ws[kk*66 + o] = g_wt[(ch*64 + kk)*64 + o];
            }
        }
        __syncthreads();
        const float* up = u_s + (w*4)*576 + ch*64;
        #pragma unroll 2
        for (int kb = 0; kb < 64; kb += 4) {
            float4 u0 = *(const float4*)(up + kb);
            float4 u1 = *(const float4*)(up +  576 + kb);
            float4 u2 = *(const float4*)(up + 1152 + kb);
            float4 u3 = *(const float4*)(up + 1728 + kb);
            float2 w0 = *(const float2*)(Ws + (kb+0)*66 + 2*l);
            float2 w1 = *(const float2*)(Ws + (kb+1)*66 + 2*l);
            float2 w2 = *(const float2*)(Ws + (kb+2)*66 + 2*l);
            float2 w3 = *(const float2*)(Ws + (kb+3)*66 + 2*l);
            acc[0] += w0.x*u0.x + w1.x*u0.y + w2.x*u0.z + w3.x*u0.w;
            acc[1] += w0.x*u1.x + w1.x*u1.y + w2.x*u1.z + w3.x*u1.w;
            acc[2] += w0.x*u2.x + w1.x*u2.y + w2.x*u2.z + w3.x*u2.w;
            acc[3] += w0.x*u3.x + w1.x*u3.y + w2.x*u3.z + w3.x*u3.w;
            acc[4] += w0.y*u0.x + w1.y*u0.y + w2.y*u0.z + w3.y*u0.w;
            acc[5] += w0.y*u1.x + w1.y*u1.y + w2.y*u1.z + w3.y*u1.w;
            acc[6] += w0.y*u2.x + w1.y*u2.y + w2.y*u2.z + w3.y*u2.w;
            acc[7] += w0.y*u3.x + w1.y*u3.y + w2.y*u3.z + w3.y*u3.w;
        }
    }

    // ---- epilogue: stage in smem, then coalesced NCHW store with bias ----
    __syncthreads();
    #pragma unroll
    for (int j = 0; j < 2; j++)
        #pragma unroll
        for (int i = 0; i < 4; i++)
            outb[(2*l + j)*33 + (w*4 + i)] = acc[j*4 + i];
    __syncthreads();
    #pragma unroll
    for (int r = 0; r < 8; r++) {
        int lin = r*256 + t;
        int o = lin >> 5, p = lin & 31;
        float be = 0.f;
        #pragma unroll
        for (int g = 0; g < 8; g++) be += wc8_s[p*8 + g] * bias[g*64 + o];
        out[((b*64 + o) << 14) + tbase + p] = outb[o*33 + p] + be;
    }
}

// ---------------- launch ----------------
extern "C" void kernel_launch(void* const* d_in, const int* in_sizes, int n_in,
                              void* d_out, int out_size) {
    const float* input  = (const float*)d_in[0];
    const float* offset = (const float*)d_in[1];
    const float* maskp  = (const float*)d_in[2];
    const float* w_c8   = (const float*)d_in[3];
    const float* weight = (const float*)d_in[4];
    const float* bias   = (const float*)d_in[5];
    const float* fc_w   = (const float*)d_in[6];
    const float* fc_b   = (const float*)d_in[7];
    float* out = (float*)d_out;

    cudaFuncSetAttribute(main_kernel, cudaFuncAttributeMaxDynamicSharedMemorySize, SMEM_BYTES);

    nhwc_kernel <<<1024, 256>>>(input);
    wt_kernel   <<<144, 256>>>(weight);
    pool_kernel <<<128, 256>>>(input);
    setup_kernel<<<1, 256>>>(fc_w, fc_b);
    main_kernel <<<1024, 256, SMEM_BYTES>>>(offset, maskp, w_c8, bias, out);
}

// round 5
// speedup vs baseline: 1.1980x; 1.1725x over previous
#include <cuda_runtime.h>
#include <cstdint>
#include <math.h>

#define HH 128
#define WWD 128
#define HWP (HH*WWD)
#define BB 2

// ---------------- device scratch ----------------
__device__ float g_nhwc[BB*HWP*64];    // 8 MB, input in NHWC
__device__ float g_pooled[BB*64];      // per (b,c) plane sums
__device__ float g_Mg[8*81];           // 8 tap-transform matrices (9x9)
__device__ float g_wt[576*64];         // weight, tf32-rounded, [pos=k2*64+c][o]

#define SMV 0.20710678118654746f
#define M2V 0.08578643762690495f
__device__ const float c_Mbase[81] = {
    0.5f, SMV , 0.f , SMV , M2V , 0.f , 0.f , 0.f , 0.f ,
    0.f , 1.f , 0.f , 0.f , 0.f , 0.f , 0.f , 0.f , 0.f ,
    0.f , SMV , 0.5f, 0.f , M2V , SMV , 0.f , 0.f , 0.f ,
    0.f , 0.f , 0.f , 1.f , 0.f , 0.f , 0.f , 0.f , 0.f ,
    0.f , 0.f , 0.f , 0.f , 1.f , 0.f , 0.f , 0.f , 0.f ,
    0.f , 0.f , 0.f , 0.f , 0.f , 1.f , 0.f , 0.f , 0.f ,
    0.f , 0.f , 0.f , SMV , M2V , 0.f , 0.5f, SMV , 0.f ,
    0.f , 0.f , 0.f , 0.f , 0.f , 0.f , 0.f , 1.f , 0.f ,
    0.f , 0.f , 0.f , 0.f , M2V , SMV , 0.f , SMV , 0.5f
};

__device__ const int c_P2[8][9] = {
    {0,1,2,3,4,5,6,7,8},
    {3,0,1,6,4,2,7,8,5},
    {6,3,0,7,4,1,8,5,2},
    {7,6,3,8,4,0,5,2,1},
    {8,7,6,5,4,3,2,1,0},
    {5,8,7,2,4,6,1,0,3},
    {2,5,8,1,4,7,0,3,6},
    {1,2,5,0,4,8,3,6,7}
};

__device__ __forceinline__ uint32_t f2tf32(float v) {
    uint32_t r;
    asm("cvt.rna.tf32.f32 %0, %1;" : "=r"(r) : "f"(v));
    return r;
}

// ---------------- kernel 1: NCHW -> NHWC transpose ----------------
__global__ __launch_bounds__(256) void nhwc_kernel(const float* __restrict__ in) {
    __shared__ float tile[64][33];
    int bid = blockIdx.x;
    int b   = bid >> 9;
    int rem = bid & 511;
    int y   = rem >> 2;
    int x0  = (rem & 3) << 5;
    int t   = threadIdx.x;

    int xl = t & 31, cb = t >> 5;
    #pragma unroll
    for (int i = 0; i < 8; i++) {
        int c = cb + i*8;
        tile[c][xl] = in[(((b*64 + c)*128 + y)*128) + x0 + xl];
    }
    __syncthreads();
    int c2 = t & 63, xb = t >> 6;
    #pragma unroll
    for (int i = 0; i < 8; i++) {
        int x = xb + i*4;
        g_nhwc[(((b*128 + y)*128) + x0 + x)*64 + c2] = tile[c2][x];
    }
}

// ---------------- kernel 2: per-(b,c) plane sums ----------------
__global__ __launch_bounds__(256) void pool_kernel(const float* __restrict__ in) {
    __shared__ float red[8];
    int bc = blockIdx.x, t = threadIdx.x;
    const float* p = in + (size_t)bc * HWP;
    float s = 0.f;
    for (int i = t; i < HWP; i += 256) s += p[i];
    #pragma unroll
    for (int o = 16; o > 0; o >>= 1) s += __shfl_down_sync(0xffffffffu, s, o);
    if ((t & 31) == 0) red[t >> 5] = s;
    __syncthreads();
    if (t == 0) {
        float tot = 0.f;
        #pragma unroll
        for (int i = 0; i < 8; i++) tot += red[i];
        g_pooled[bc] = tot;
    }
}

// ---------------- kernel 3: wt transpose (blocks 0..143) + setup (block 144) ----------------
__global__ __launch_bounds__(256) void wtsetup_kernel(const float* __restrict__ w,
                                                      const float* __restrict__ fc_w,
                                                      const float* __restrict__ fc_b) {
    int t = threadIdx.x;
    if (blockIdx.x < 144) {
        int e = blockIdx.x*256 + t;            // 36864 = 64 o * 576
        int o = e / 576, j = e - o*576;        // j = c*9 + k2 (coalesced read)
        int c = j / 9, k2 = j - c*9;
        g_wt[(k2*64 + c)*64 + o] = __uint_as_float(f2tf32(w[e]));
    } else {
        __shared__ float r_s[4];
        if (t < 128) {                          // warp per fc row, lane per 2 channels
            int t4 = t >> 5, l = t & 31;
            const float inv = 1.f / (float)HWP;
            float p0 = (g_pooled[2*l]   + g_pooled[64 + 2*l])   * inv;
            float p1 = (g_pooled[2*l+1] + g_pooled[64 + 2*l+1]) * inv;
            float s = p0 * fc_w[t4*64 + 2*l] + p1 * fc_w[t4*64 + 2*l+1];
            #pragma unroll
            for (int o = 16; o > 0; o >>= 1) s += __shfl_down_sync(0xffffffffu, s, o);
            if (l == 0) r_s[t4] = 1.f / (1.f + expf(-(s + fc_b[t4])));
        }
        __syncthreads();
        for (int e = t; e < 648; e += 256) {
            int g = e / 81, kk = e % 81;
            int k = kk / 9, k2 = kk % 9;
            int pk = c_P2[g][k];
            float mb = c_Mbase[pk*9 + k2];
            float v;
            if ((g & 1) == 0) {
                float rr = r_s[g >> 1];
                v = rr * mb + (1.f - rr) * ((k2 == pk) ? 1.f : 0.f);
            } else {
                v = mb;
            }
            g_Mg[e] = v;
        }
    }
}

// ---------------- kernel 4: fused DCN (sample + transform + tf32 MMA GEMM) ----------------
// smem (floats), total 25672:
//   U_OFF    0      : u_s[32 px][578]  (pos = k2*64 + c, tf32 bits)
//   A_OFF    18496  : A_s[32][9][12]        (phase0/1)  } aliased in phase2 by:
//   IDX_OFF  22080  : idx_s[32*9][4] ints   (phase0/1)  }  WBS_OFF 18496 Wbs[64][66]
//   WGT_OFF  23232  : wgt_s[32*9][4]        (phase0/1)  }  OUTB_OFF 22720 outb[64][33]
//   WC8_OFF  24896  : wc8T[8][33]           (persists)
//   BIAS_OFF 25160  : bias_s[512]           (persists)
#define U_OFF    0
#define A_OFF    18496
#define IDX_OFF  22080
#define WGT_OFF  23232
#define WBS_OFF  18496
#define OUTB_OFF 22720
#define WC8_OFF  24896
#define BIAS_OFF 25160
#define SMEM_FLOATS 25672
#define SMEM_BYTES  (SMEM_FLOATS*4)

__global__ __launch_bounds__(256, 2) void main_kernel(
    const float* __restrict__ offset, const float* __restrict__ mask,
    const float* __restrict__ wc8g,   const float* __restrict__ bias,
    float* __restrict__ out)
{
    extern __shared__ float sm[];
    float* u_s   = sm + U_OFF;
    float* A_s   = sm + A_OFF;
    int*   idx_s = (int*)(sm + IDX_OFF);
    float* wgt_s = sm + WGT_OFF;
    float* Wbs   = sm + WBS_OFF;
    float* outb  = sm + OUTB_OFF;
    float* wc8T  = sm + WC8_OFF;
    float* bias_s= sm + BIAS_OFF;

    int t     = threadIdx.x;
    int bid   = blockIdx.x;               // 1024: b(2) * 512 tiles
    int b     = bid >> 9;
    int tbase = (bid & 511) << 5;
    int h     = tbase >> 7;
    int w0    = tbase & 127;
    int w     = t >> 5;
    int l     = t & 31;

    // ---- phase 0a: wc8 (transposed), bias staging ----
    wc8T[w*33 + l] = wc8g[((b*8 + w) << 14) + tbase + l];
    bias_s[t]       = bias[t];
    bias_s[t + 256] = bias[t + 256];

    // ---- phase 0b: bilinear indices & weights (mask folded) ----
    for (int task = t; task < 288; task += 256) {
        int p = task & 31, k = task >> 5;
        int pix = tbase + p;
        float offy = offset[((b*18 + 2*k    ) << 14) + pix];
        float offx = offset[((b*18 + 2*k + 1) << 14) + pix];
        float mval = mask  [((b*9  + k      ) << 14) + pix];
        float py = (float)h        + (float)(k/3) - 1.f + offy;
        float px = (float)(w0 + p) + (float)(k%3) - 1.f + offx;
        float y0f = floorf(py), x0f = floorf(px);
        float ly = py - y0f, lx = px - x0f;
        int y0 = (int)y0f, x0i = (int)x0f;
        int y1 = y0 + 1, x1 = x0i + 1;
        bool vy0 = (y0 >= 0) & (y0 <= 127);
        bool vy1 = (y1 >= 0) & (y1 <= 127);
        bool vx0 = (x0i >= 0) & (x0i <= 127);
        bool vx1 = (x1 >= 0) & (x1 <= 127);
        float w00 = (1.f-ly)*(1.f-lx) * ((vy0 & vx0) ? mval : 0.f);
        float w01 = (1.f-ly)*lx       * ((vy0 & vx1) ? mval : 0.f);
        float w10 = ly*(1.f-lx)       * ((vy1 & vx0) ? mval : 0.f);
        float w11 = ly*lx             * ((vy1 & vx1) ? mval : 0.f);
        int cy0 = min(max(y0, 0), 127), cy1 = min(max(y1, 0), 127);
        int cx0 = min(max(x0i,0), 127), cx1 = min(max(x1, 0), 127);
        int b4 = (p*9 + k)*4;
        idx_s[b4+0] = cy0*128 + cx0;
        idx_s[b4+1] = cy0*128 + cx1;
        idx_s[b4+2] = cy1*128 + cx0;
        idx_s[b4+3] = cy1*128 + cx1;
        wgt_s[b4+0] = w00; wgt_s[b4+1] = w01; wgt_s[b4+2] = w10; wgt_s[b4+3] = w11;
    }
    __syncthreads();

    // ---- phase 0c: A[p][k][k2] = sum_g wc8[g] * M_g ----
    for (int e = t; e < 2592; e += 256) {
        int p = e & 31, kk = e >> 5;
        int k = kk / 9, k2 = kk - k*9;
        float a = 0.f;
        #pragma unroll
        for (int g = 0; g < 8; g++) a += wc8T[g*33 + p] * g_Mg[g*81 + kk];
        A_s[p*112 + k*12 + k2] = a;
    }
    __syncthreads();

    // ---- phase 1: gather + bilinear + tap transform -> u_s (tf32 bits) ----
    {
        const float2* ib = (const float2*)(g_nhwc + ((size_t)b << 20));
        const int4*   idx4 = (const int4*)idx_s;
        const float4* wgt4 = (const float4*)wgt_s;
        #pragma unroll
        for (int pp = 0; pp < 4; pp++) {
            int p = w*4 + pp;
            float2 ua[9];
            #pragma unroll
            for (int i = 0; i < 9; i++) { ua[i].x = 0.f; ua[i].y = 0.f; }
            #pragma unroll
            for (int k = 0; k < 9; k++) {
                int4   id = idx4[p*9 + k];
                float4 wg = wgt4[p*9 + k];
                float2 c00 = ib[id.x*32 + l];
                float2 c01 = ib[id.y*32 + l];
                float2 c10 = ib[id.z*32 + l];
                float2 c11 = ib[id.w*32 + l];
                float vx = wg.x*c00.x + wg.y*c01.x + wg.z*c10.x + wg.w*c11.x;
                float vy = wg.x*c00.y + wg.y*c01.y + wg.z*c10.y + wg.w*c11.y;
                const float* Ab = A_s + p*112 + k*12;
                float4 a0 = *(const float4*)(Ab);
                float4 a1 = *(const float4*)(Ab + 4);
                float  a8 = Ab[8];
                ua[0].x += a0.x*vx; ua[0].y += a0.x*vy;
                ua[1].x += a0.y*vx; ua[1].y += a0.y*vy;
                ua[2].x += a0.z*vx; ua[2].y += a0.z*vy;
                ua[3].x += a0.w*vx; ua[3].y += a0.w*vy;
                ua[4].x += a1.x*vx; ua[4].y += a1.x*vy;
                ua[5].x += a1.y*vx; ua[5].y += a1.y*vy;
                ua[6].x += a1.z*vx; ua[6].y += a1.z*vy;
                ua[7].x += a1.w*vx; ua[7].y += a1.w*vy;
                ua[8].x += a8  *vx; ua[8].y += a8  *vy;
            }
            // store: pos = k2*64 + c; lane owns channels 2l,2l+1 -> float2 at k2*64+2l
            float* urow = u_s + p*578;
            #pragma unroll
            for (int k2 = 0; k2 < 9; k2++) {
                float2 v;
                v.x = __uint_as_float(f2tf32(ua[k2].x));
                v.y = __uint_as_float(f2tf32(ua[k2].y));
                *(float2*)(urow + k2*64 + 2*l) = v;
            }
        }
    }

    // ---- phase 2: tf32 MMA  D[32px x 64o] = u[32 x 576] * Wt[576 x 64] ----
    // warp w: px rows m0..m0+15 (m0=(w&1)*16), o cols n0..n0+15 (n0=(w>>1)*16)
    int m0 = (w & 1) * 16;
    int n0 = (w >> 1) * 16;
    int g  = l >> 2;        // groupID
    int tq = l & 3;         // threadID_in_group
    float acc[2][4];
    #pragma unroll
    for (int j = 0; j < 2; j++)
        #pragma unroll
        for (int i = 0; i < 4; i++) acc[j][i] = 0.f;

    for (int ch = 0; ch < 9; ch++) {
        __syncthreads();   // previous chunk's Wbs consumed / phase0-1 scratch dead
        {
            const float* slab = g_wt + ch*4096;   // [64 kk][64 o] contiguous
            #pragma unroll
            for (int i = 0; i < 16; i++) {
                int lin = i*256 + t;
                Wbs[(lin >> 6)*66 + (lin & 63)] = slab[lin];
            }
        }
        __syncthreads();
        const float* uaP  = u_s + (m0 + g)*578 + ch*64 + tq;
        const float* uaP8 = uaP + 8*578;
        #pragma unroll
        for (int ks = 0; ks < 8; ks++) {
            uint32_t a0 = __float_as_uint(uaP [ks*8    ]);
            uint32_t a1 = __float_as_uint(uaP8[ks*8    ]);
            uint32_t a2 = __float_as_uint(uaP [ks*8 + 4]);
            uint32_t a3 = __float_as_uint(uaP8[ks*8 + 4]);
            const float* wrow0 = Wbs + (ks*8 + tq)*66 + n0 + g;
            const float* wrow1 = wrow0 + 4*66;
            #pragma unroll
            for (int j = 0; j < 2; j++) {
                uint32_t b0 = __float_as_uint(wrow0[j*8]);
                uint32_t b1 = __float_as_uint(wrow1[j*8]);
                asm volatile(
                    "mma.sync.aligned.m16n8k8.row.col.f32.tf32.tf32.f32 "
                    "{%0,%1,%2,%3}, {%4,%5,%6,%7}, {%8,%9}, {%0,%1,%2,%3};\n"
                    : "+f"(acc[j][0]), "+f"(acc[j][1]), "+f"(acc[j][2]), "+f"(acc[j][3])
                    : "r"(a0), "r"(a1), "r"(a2), "r"(a3), "r"(b0), "r"(b1));
            }
        }
    }

    // ---- epilogue: stage D in smem (outb[o][px]), coalesced NCHW store + bias ----
    __syncthreads();
    #pragma unroll
    for (int j = 0; j < 2; j++) {
        int nb = n0 + j*8 + 2*tq;
        outb[(nb    )*33 + m0 + g    ] = acc[j][0];
        outb[(nb + 1)*33 + m0 + g    ] = acc[j][1];
        outb[(nb    )*33 + m0 + g + 8] = acc[j][2];
        outb[(nb + 1)*33 + m0 + g + 8] = acc[j][3];
    }
    __syncthreads();
    #pragma unroll
    for (int r = 0; r < 8; r++) {
        int o = r*8 + w;       // constant per warp
        int p = l;
        float be = 0.f;
        #pragma unroll
        for (int gg = 0; gg < 8; gg++) be += wc8T[gg*33 + p] * bias_s[gg*64 + o];
        out[((b*64 + o) << 14) + tbase + p] = outb[o*33 + p] + be;
    }
}

// ---------------- launch ----------------
extern "C" void kernel_launch(void* const* d_in, const int* in_sizes, int n_in,
                              void* d_out, int out_size) {
    const float* input  = (const float*)d_in[0];
    const float* offset = (const float*)d_in[1];
    const float* maskp  = (const float*)d_in[2];
    const float* w_c8   = (const float*)d_in[3];
    const float* weight = (const float*)d_in[4];
    const float* bias   = (const float*)d_in[5];
    const float* fc_w   = (const float*)d_in[6];
    const float* fc_b   = (const float*)d_in[7];
    float* out = (float*)d_out;

    cudaFuncSetAttribute(main_kernel, cudaFuncAttributeMaxDynamicSharedMemorySize, SMEM_BYTES);

    nhwc_kernel   <<<1024, 256>>>(input);
    pool_kernel   <<<128, 256>>>(input);
    wtsetup_kernel<<<145, 256>>>(weight, fc_w, fc_b);
    main_kernel   <<<1024, 256, SMEM_BYTES>>>(offset, maskp, w_c8, bias, out);
}

// round 7
// speedup vs baseline: 1.7090x; 1.4265x over previous
#include <cuda_runtime.h>
#include <cstdint>
#include <math.h>

#define HH 128
#define WWD 128
#define HWP (HH*WWD)
#define BB 2

// ---------------- device scratch ----------------
__device__ float g_nhwc[BB*HWP*64];    // 8 MB, input in NHWC
__device__ float g_pooled[BB*64];      // per (b,c) plane sums
__device__ float g_Mg[8*81];           // 8 tap-transform matrices (9x9)
__device__ float g_wt[9*64*64];        // weight tf32, [k2 slab][o 64][c 64]

#define SMV 0.20710678118654746f
#define M2V 0.08578643762690495f
__device__ const float c_Mbase[81] = {
    0.5f, SMV , 0.f , SMV , M2V , 0.f , 0.f , 0.f , 0.f ,
    0.f , 1.f , 0.f , 0.f , 0.f , 0.f , 0.f , 0.f , 0.f ,
    0.f , SMV , 0.5f, 0.f , M2V , SMV , 0.f , 0.f , 0.f ,
    0.f , 0.f , 0.f , 1.f , 0.f , 0.f , 0.f , 0.f , 0.f ,
    0.f , 0.f , 0.f , 0.f , 1.f , 0.f , 0.f , 0.f , 0.f ,
    0.f , 0.f , 0.f , 0.f , 0.f , 1.f , 0.f , 0.f , 0.f ,
    0.f , 0.f , 0.f , SMV , M2V , 0.f , 0.5f, SMV , 0.f ,
    0.f , 0.f , 0.f , 0.f , 0.f , 0.f , 0.f , 1.f , 0.f ,
    0.f , 0.f , 0.f , 0.f , M2V , SMV , 0.f , SMV , 0.5f
};

__device__ const int c_P2[8][9] = {
    {0,1,2,3,4,5,6,7,8},
    {3,0,1,6,4,2,7,8,5},
    {6,3,0,7,4,1,8,5,2},
    {7,6,3,8,4,0,5,2,1},
    {8,7,6,5,4,3,2,1,0},
    {5,8,7,2,4,6,1,0,3},
    {2,5,8,1,4,7,0,3,6},
    {1,2,5,0,4,8,3,6,7}
};

__device__ __forceinline__ uint32_t f2tf32(float v) {
    uint32_t r;
    asm("cvt.rna.tf32.f32 %0, %1;" : "=r"(r) : "f"(v));
    return r;
}

// ---------------- kernel 1: NCHW -> NHWC transpose ----------------
__global__ __launch_bounds__(256) void nhwc_kernel(const float* __restrict__ in) {
    __shared__ float tile[64][33];
    int bid = blockIdx.x;
    int b   = bid >> 9;
    int rem = bid & 511;
    int y   = rem >> 2;
    int x0  = (rem & 3) << 5;
    int t   = threadIdx.x;

    int xl = t & 31, cb = t >> 5;
    #pragma unroll
    for (int i = 0; i < 8; i++) {
        int c = cb + i*8;
        tile[c][xl] = in[(((b*64 + c)*128 + y)*128) + x0 + xl];
    }
    __syncthreads();
    int c2 = t & 63, xb = t >> 6;
    #pragma unroll
    for (int i = 0; i < 8; i++) {
        int x = xb + i*4;
        g_nhwc[(((b*128 + y)*128) + x0 + x)*64 + c2] = tile[c2][x];
    }
}

// ---------------- kernel 2: per-(b,c) plane sums ----------------
__global__ __launch_bounds__(256) void pool_kernel(const float* __restrict__ in) {
    __shared__ float red[8];
    int bc = blockIdx.x, t = threadIdx.x;
    const float* p = in + (size_t)bc * HWP;
    float s = 0.f;
    for (int i = t; i < HWP; i += 256) s += p[i];
    #pragma unroll
    for (int o = 16; o > 0; o >>= 1) s += __shfl_down_sync(0xffffffffu, s, o);
    if ((t & 31) == 0) red[t >> 5] = s;
    __syncthreads();
    if (t == 0) {
        float tot = 0.f;
        #pragma unroll
        for (int i = 0; i < 8; i++) tot += red[i];
        g_pooled[bc] = tot;
    }
}

// ---------------- kernel 3: wt re-layout (blocks 0..143) + setup (block 144) ----------------
__global__ __launch_bounds__(256) void wtsetup_kernel(const float* __restrict__ w,
                                                      const float* __restrict__ fc_w,
                                                      const float* __restrict__ fc_b) {
    int t = threadIdx.x;
    if (blockIdx.x < 144) {
        int e = blockIdx.x*256 + t;            // 36864 = 64 o * 576
        int o = e / 576, j = e - o*576;        // j = c*9 + k2 (coalesced read)
        int c = j / 9, k2 = j - c*9;
        g_wt[(k2*64 + o)*64 + c] = __uint_as_float(f2tf32(w[e]));
    } else {
        __shared__ float r_s[4];
        if (t < 128) {                          // warp per fc row, lane per 2 channels
            int t4 = t >> 5, l = t & 31;
            const float inv = 1.f / (float)HWP;
            float p0 = (g_pooled[2*l]   + g_pooled[64 + 2*l])   * inv;
            float p1 = (g_pooled[2*l+1] + g_pooled[64 + 2*l+1]) * inv;
            float s = p0 * fc_w[t4*64 + 2*l] + p1 * fc_w[t4*64 + 2*l+1];
            #pragma unroll
            for (int o = 16; o > 0; o >>= 1) s += __shfl_down_sync(0xffffffffu, s, o);
            if (l == 0) r_s[t4] = 1.f / (1.f + expf(-(s + fc_b[t4])));
        }
        __syncthreads();
        for (int e = t; e < 648; e += 256) {
            int g = e / 81, kk = e % 81;
            int k = kk / 9, k2 = kk % 9;
            int pk = c_P2[g][k];
            float mb = c_Mbase[pk*9 + k2];
            float v;
            if ((g & 1) == 0) {
                float rr = r_s[g >> 1];
                v = rr * mb + (1.f - rr) * ((k2 == pk) ? 1.f : 0.f);
            } else {
                v = mb;
            }
            g_Mg[e] = v;
        }
    }
}

// ---------------- kernel 4: fused DCN (sample + transform + tf32 MMA GEMM) ----------------
// smem (floats), total 25224:
//   U_OFF    0      : u_s[32 px][580]  (slab k2 at +k2*64; tf32 bits)
//   A_OFF    18560  : A_s[32][9][12]      (phase0/1) -- aliased by outb[64][33] in epilogue
//   IDX_OFF  22144  : idx_s[32*9][4] ints (phase0/1)
//   WGT_OFF  23296  : wgt_s[32*9][4]      (phase0/1)
//   WC8_OFF  24448  : wc8T[8][33]         (persists)
//   BIAS_OFF 24712  : bias_s[512]         (persists)
#define U_OFF    0
#define USTRIDE  580
#define A_OFF    18560
#define IDX_OFF  22144
#define WGT_OFF  23296
#define OUTB_OFF 18560
#define WC8_OFF  24448
#define BIAS_OFF 24712
#define SMEM_FLOATS 25224
#define SMEM_BYTES  (SMEM_FLOATS*4)

__global__ __launch_bounds__(256, 2) void main_kernel(
    const float* __restrict__ offset, const float* __restrict__ mask,
    const float* __restrict__ wc8g,   const float* __restrict__ bias,
    float* __restrict__ out)
{
    extern __shared__ float sm[];
    float* u_s   = sm + U_OFF;
    float* A_s   = sm + A_OFF;
    int*   idx_s = (int*)(sm + IDX_OFF);
    float* wgt_s = sm + WGT_OFF;
    float* outb  = sm + OUTB_OFF;
    float* wc8T  = sm + WC8_OFF;
    float* bias_s= sm + BIAS_OFF;

    int t     = threadIdx.x;
    int bid   = blockIdx.x;               // 1024: b(2) * 512 tiles
    int b     = bid >> 9;
    int tbase = (bid & 511) << 5;
    int h     = tbase >> 7;
    int w0    = tbase & 127;
    int w     = t >> 5;
    int l     = t & 31;

    // ---- phase 0a: wc8 (transposed), bias staging ----
    wc8T[w*33 + l] = wc8g[((b*8 + w) << 14) + tbase + l];
    bias_s[t]       = bias[t];
    bias_s[t + 256] = bias[t + 256];

    // ---- phase 0b: bilinear indices & weights (mask folded) ----
    for (int task = t; task < 288; task += 256) {
        int p = task & 31, k = task >> 5;
        int pix = tbase + p;
        float offy = offset[((b*18 + 2*k    ) << 14) + pix];
        float offx = offset[((b*18 + 2*k + 1) << 14) + pix];
        float mval = mask  [((b*9  + k      ) << 14) + pix];
        float py = (float)h        + (float)(k/3) - 1.f + offy;
        float px = (float)(w0 + p) + (float)(k%3) - 1.f + offx;
        float y0f = floorf(py), x0f = floorf(px);
        float ly = py - y0f, lx = px - x0f;
        int y0 = (int)y0f, x0i = (int)x0f;
        int y1 = y0 + 1, x1 = x0i + 1;
        bool vy0 = (y0 >= 0) & (y0 <= 127);
        bool vy1 = (y1 >= 0) & (y1 <= 127);
        bool vx0 = (x0i >= 0) & (x0i <= 127);
        bool vx1 = (x1 >= 0) & (x1 <= 127);
        float w00 = (1.f-ly)*(1.f-lx) * ((vy0 & vx0) ? mval : 0.f);
        float w01 = (1.f-ly)*lx       * ((vy0 & vx1) ? mval : 0.f);
        float w10 = ly*(1.f-lx)       * ((vy1 & vx0) ? mval : 0.f);
        float w11 = ly*lx             * ((vy1 & vx1) ? mval : 0.f);
        int cy0 = min(max(y0, 0), 127), cy1 = min(max(y1, 0), 127);
        int cx0 = min(max(x0i,0), 127), cx1 = min(max(x1, 0), 127);
        int b4 = (p*9 + k)*4;
        idx_s[b4+0] = cy0*128 + cx0;
        idx_s[b4+1] = cy0*128 + cx1;
        idx_s[b4+2] = cy1*128 + cx0;
        idx_s[b4+3] = cy1*128 + cx1;
        wgt_s[b4+0] = w00; wgt_s[b4+1] = w01; wgt_s[b4+2] = w10; wgt_s[b4+3] = w11;
    }
    __syncthreads();

    // ---- phase 0c: A[p][k][k2] = sum_g wc8[g] * M_g ----
    for (int e = t; e < 2592; e += 256) {
        int p = e & 31, kk = e >> 5;
        int k = kk / 9, k2 = kk - k*9;
        float a = 0.f;
        #pragma unroll
        for (int g = 0; g < 8; g++) a += wc8T[g*33 + p] * g_Mg[g*81 + kk];
        A_s[p*112 + k*12 + k2] = a;
    }
    __syncthreads();

    // ---- phase 1: gather + bilinear + tap transform -> u_s (tf32 bits) ----
    {
        const float2* ib = (const float2*)(g_nhwc + ((size_t)b << 20));
        const int4*   idx4 = (const int4*)idx_s;
        const float4* wgt4 = (const float4*)wgt_s;
        #pragma unroll
        for (int pp = 0; pp < 4; pp++) {
            int p = w*4 + pp;
            float2 ua[9];
            #pragma unroll
            for (int i = 0; i < 9; i++) { ua[i].x = 0.f; ua[i].y = 0.f; }
            #pragma unroll
            for (int k = 0; k < 9; k++) {
                int4   id = idx4[p*9 + k];
                float4 wg = wgt4[p*9 + k];
                float2 c00 = ib[id.x*32 + l];
                float2 c01 = ib[id.y*32 + l];
                float2 c10 = ib[id.z*32 + l];
                float2 c11 = ib[id.w*32 + l];
                float vx = wg.x*c00.x + wg.y*c01.x + wg.z*c10.x + wg.w*c11.x;
                float vy = wg.x*c00.y + wg.y*c01.y + wg.z*c10.y + wg.w*c11.y;
                const float* Ab = A_s + p*112 + k*12;
                float4 a0 = *(const float4*)(Ab);
                float4 a1 = *(const float4*)(Ab + 4);
                float  a8 = Ab[8];
                ua[0].x += a0.x*vx; ua[0].y += a0.x*vy;
                ua[1].x += a0.y*vx; ua[1].y += a0.y*vy;
                ua[2].x += a0.z*vx; ua[2].y += a0.z*vy;
                ua[3].x += a0.w*vx; ua[3].y += a0.w*vy;
                ua[4].x += a1.x*vx; ua[4].y += a1.x*vy;
                ua[5].x += a1.y*vx; ua[5].y += a1.y*vy;
                ua[6].x += a1.z*vx; ua[6].y += a1.z*vy;
                ua[7].x += a1.w*vx; ua[7].y += a1.w*vy;
                ua[8].x += a8  *vx; ua[8].y += a8  *vy;
            }
            // store: slab = k2; channels 2l,2l+1 at phys cols 2l,2l+1
            float* urow = u_s + p*USTRIDE;
            #pragma unroll
            for (int k2 = 0; k2 < 9; k2++) {
                float2 v;
                v.x = __uint_as_float(f2tf32(ua[k2].x));
                v.y = __uint_as_float(f2tf32(ua[k2].y));
                *(float2*)(urow + k2*64 + 2*l) = v;
            }
        }
    }
    __syncthreads();

    // ---- phase 2: tf32 MMA  D[32px x 64o] = u[32 x 576] * Wt[576 x 64]  (no barriers) ----
    // warp w: px rows m0..m0+15 (m0=(w&1)*16), o cols n0..n0+15 (n0=(w>>1)*16)
    int m0 = (w & 1) * 16;
    int n0 = (w >> 1) * 16;
    int g  = l >> 2;        // groupID
    int tq = l & 3;         // threadID_in_group
    // swizzled chunk offsets (floats): chunk cc=4tq+i -> swz(cc)=cc^(((cc>>3)&1)<<1)
    int ci[4];
    #pragma unroll
    for (int i = 0; i < 4; i++) {
        int cc = 4*tq + i;
        ci[i] = (cc ^ (((cc >> 3) & 1) << 1)) * 4;
    }
    float acc[2][4];
    #pragma unroll
    for (int j = 0; j < 2; j++)
        #pragma unroll
        for (int i = 0; i < 4; i++) acc[j][i] = 0.f;

    for (int ch = 0; ch < 9; ch++) {
        const float* Wr = g_wt + (ch*64 + n0 + g)*64;
        const float* Ur = u_s + (m0 + g)*USTRIDE + ch*64;
        float4 A0[4], A1[4], B0[4], B1[4];
        #pragma unroll
        for (int i = 0; i < 4; i++) {
            B0[i] = *(const float4*)(Wr + ci[i]);
            B1[i] = *(const float4*)(Wr + 512 + ci[i]);        // +8 rows * 64
            A0[i] = *(const float4*)(Ur + ci[i]);
            A1[i] = *(const float4*)(Ur + 8*USTRIDE + ci[i]);
        }
        const float* A0f = (const float*)A0;
        const float* A1f = (const float*)A1;
        const float* B0f = (const float*)B0;
        const float* B1f = (const float*)B1;
        #pragma unroll
        for (int ks = 0; ks < 8; ks++) {
            int ii = (ks >> 1)*4 + (ks & 1)*2;
            uint32_t a0 = __float_as_uint(A0f[ii]);
            uint32_t a1 = __float_as_uint(A1f[ii]);
            uint32_t a2 = __float_as_uint(A0f[ii+1]);
            uint32_t a3 = __float_as_uint(A1f[ii+1]);
            uint32_t b0 = __float_as_uint(B0f[ii]);
            uint32_t b1 = __float_as_uint(B0f[ii+1]);
            asm volatile(
                "mma.sync.aligned.m16n8k8.row.col.f32.tf32.tf32.f32 "
                "{%0,%1,%2,%3}, {%4,%5,%6,%7}, {%8,%9}, {%0,%1,%2,%3};\n"
                : "+f"(acc[0][0]), "+f"(acc[0][1]), "+f"(acc[0][2]), "+f"(acc[0][3])
                : "r"(a0), "r"(a1), "r"(a2), "r"(a3), "r"(b0), "r"(b1));
            uint32_t b2 = __float_as_uint(B1f[ii]);
            uint32_t b3 = __float_as_uint(B1f[ii+1]);
            asm volatile(
                "mma.sync.aligned.m16n8k8.row.col.f32.tf32.tf32.f32 "
                "{%0,%1,%2,%3}, {%4,%5,%6,%7}, {%8,%9}, {%0,%1,%2,%3};\n"
                : "+f"(acc[1][0]), "+f"(acc[1][1]), "+f"(acc[1][2]), "+f"(acc[1][3])
                : "r"(a0), "r"(a1), "r"(a2), "r"(a3), "r"(b2), "r"(b3));
        }
    }

    // ---- epilogue: stage D in smem (outb[o][px]), coalesced NCHW store + bias ----
    __syncthreads();
    #pragma unroll
    for (int j = 0; j < 2; j++) {
        int nb = n0 + j*8 + 2*tq;
        outb[(nb    )*33 + m0 + g    ] = acc[j][0];
        outb[(nb + 1)*33 + m0 + g    ] = acc[j][1];
        outb[(nb    )*33 + m0 + g + 8] = acc[j][2];
        outb[(nb + 1)*33 + m0 + g + 8] = acc[j][3];
    }
    __syncthreads();
    #pragma unroll
    for (int r = 0; r < 8; r++) {
        int o = r*8 + w;       // constant per warp
        int p = l;
        float be = 0.f;
        #pragma unroll
        for (int gg = 0; gg < 8; gg++) be += wc8T[gg*33 + p] * bias_s[gg*64 + o];
        out[((b*64 + o) << 14) + tbase + p] = outb[o*33 + p] + be;
    }
}

// ---------------- launch ----------------
extern "C" void kernel_launch(void* const* d_in, const int* in_sizes, int n_in,
                              void* d_out, int out_size) {
    const float* input  = (const float*)d_in[0];
    const float* offset = (const float*)d_in[1];
    const float* maskp  = (const float*)d_in[2];
    const float* w_c8   = (const float*)d_in[3];
    const float* weight = (const float*)d_in[4];
    const float* bias   = (const float*)d_in[5];
    const float* fc_w   = (const float*)d_in[6];
    const float* fc_b   = (const float*)d_in[7];
    float* out = (float*)d_out;

    cudaFuncSetAttribute(main_kernel, cudaFuncAttributeMaxDynamicSharedMemorySize, SMEM_BYTES);

    nhwc_kernel   <<<1024, 256>>>(input);
    pool_kernel   <<<128, 256>>>(input);
    wtsetup_kernel<<<145, 256>>>(weight, fc_w, fc_b);
    main_kernel   <<<1024, 256, SMEM_BYTES>>>(offset, maskp, w_c8, bias, out);
}

// round 9
// speedup vs baseline: 2.0762x; 1.2149x over previous
#include <cuda_runtime.h>
#include <cuda_fp16.h>
#include <cstdint>
#include <math.h>

#define HH 128
#define WWD 128
#define HWP (HH*WWD)
#define BB 2

// ---------------- device scratch ----------------
__device__ float g_nhwc[BB*HWP*64];    // 8 MB, input in NHWC
__device__ float g_pooled[BB*64];      // per (b,c) plane sums
__device__ float g_Mg[8*81];           // 8 tap-transform matrices (9x9)
__device__ __half g_wtf[9*4*32*32];    // W in per-lane fragment stream [slab][n0i][lane][32 halves]

#define SMV 0.20710678118654746f
#define M2V 0.08578643762690495f
__device__ const float c_Mbase[81] = {
    0.5f, SMV , 0.f , SMV , M2V , 0.f , 0.f , 0.f , 0.f ,
    0.f , 1.f , 0.f , 0.f , 0.f , 0.f , 0.f , 0.f , 0.f ,
    0.f , SMV , 0.5f, 0.f , M2V , SMV , 0.f , 0.f , 0.f ,
    0.f , 0.f , 0.f , 1.f , 0.f , 0.f , 0.f , 0.f , 0.f ,
    0.f , 0.f , 0.f , 0.f , 1.f , 0.f , 0.f , 0.f , 0.f ,
    0.f , 0.f , 0.f , 0.f , 0.f , 1.f , 0.f , 0.f , 0.f ,
    0.f , 0.f , 0.f , SMV , M2V , 0.f , 0.5f, SMV , 0.f ,
    0.f , 0.f , 0.f , 0.f , 0.f , 0.f , 0.f , 1.f , 0.f ,
    0.f , 0.f , 0.f , 0.f , M2V , SMV , 0.f , SMV , 0.5f
};

__device__ const int c_P2[8][9] = {
    {0,1,2,3,4,5,6,7,8},
    {3,0,1,6,4,2,7,8,5},
    {6,3,0,7,4,1,8,5,2},
    {7,6,3,8,4,0,5,2,1},
    {8,7,6,5,4,3,2,1,0},
    {5,8,7,2,4,6,1,0,3},
    {2,5,8,1,4,7,0,3,6},
    {1,2,5,0,4,8,3,6,7}
};

// ---------------- kernel 1: NCHW -> NHWC transpose ----------------
__global__ __launch_bounds__(256) void nhwc_kernel(const float* __restrict__ in) {
    __shared__ float tile[64][33];
    int bid = blockIdx.x;
    int b   = bid >> 9;
    int rem = bid & 511;
    int y   = rem >> 2;
    int x0  = (rem & 3) << 5;
    int t   = threadIdx.x;

    int xl = t & 31, cb = t >> 5;
    #pragma unroll
    for (int i = 0; i < 8; i++) {
        int c = cb + i*8;
        tile[c][xl] = in[(((b*64 + c)*128 + y)*128) + x0 + xl];
    }
    __syncthreads();
    int c2 = t & 63, xb = t >> 6;
    #pragma unroll
    for (int i = 0; i < 8; i++) {
        int x = xb + i*4;
        g_nhwc[(((b*128 + y)*128) + x0 + x)*64 + c2] = tile[c2][x];
    }
}

// ---------------- kernel 2: per-(b,c) plane sums ----------------
__global__ __launch_bounds__(256) void pool_kernel(const float* __restrict__ in) {
    __shared__ float red[8];
    int bc = blockIdx.x, t = threadIdx.x;
    const float* p = in + (size_t)bc * HWP;
    float s = 0.f;
    for (int i = t; i < HWP; i += 256) s += p[i];
    #pragma unroll
    for (int o = 16; o > 0; o >>= 1) s += __shfl_down_sync(0xffffffffu, s, o);
    if ((t & 31) == 0) red[t >> 5] = s;
    __syncthreads();
    if (t == 0) {
        float tot = 0.f;
        #pragma unroll
        for (int i = 0; i < 8; i++) tot += red[i];
        g_pooled[bc] = tot;
    }
}

// ---------------- kernel 3: W fragment stream (blocks 0..143) + setup (block 144) ----------------
// g_wtf flat index f = slab*4096 + n0i*1024 + lane*32 + e
//   e = j*16 + s*4 + pair*2 + within
//   o  = n0i*16 + j*8 + (lane>>2)
//   ch = 2*(lane&3) + 16*s + 8*pair + within      (ch = within-slab channel c)
//   value = weight[o][c=ch][k2=slab]  (weight layout o*576 + c*9 + k2)
__global__ __launch_bounds__(256) void wtsetup_kernel(const float* __restrict__ w,
                                                      const float* __restrict__ fc_w,
                                                      const float* __restrict__ fc_b) {
    int t = threadIdx.x;
    if (blockIdx.x < 144) {
        int f = blockIdx.x*256 + t;            // 36864 elements
        int e    = f & 31;
        int lane = (f >> 5) & 31;
        int n0i  = (f >> 10) & 3;
        int slab = f >> 12;
        int j = e >> 4, r = e & 15;
        int s = r >> 2, pair = (r >> 1) & 1, within = r & 1;
        int g = lane >> 2, tq = lane & 3;
        int o  = n0i*16 + j*8 + g;
        int ch = 2*tq + 16*s + 8*pair + within;
        g_wtf[f] = __float2half_rn(w[o*576 + ch*9 + slab]);
    } else {
        __shared__ float r_s[4];
        if (t < 128) {                          // warp per fc row, lane per 2 channels
            int t4 = t >> 5, l = t & 31;
            const float inv = 1.f / (float)HWP;
            float p0 = (g_pooled[2*l]   + g_pooled[64 + 2*l])   * inv;
            float p1 = (g_pooled[2*l+1] + g_pooled[64 + 2*l+1]) * inv;
            float s = p0 * fc_w[t4*64 + 2*l] + p1 * fc_w[t4*64 + 2*l+1];
            #pragma unroll
            for (int o = 16; o > 0; o >>= 1) s += __shfl_down_sync(0xffffffffu, s, o);
            if (l == 0) r_s[t4] = 1.f / (1.f + expf(-(s + fc_b[t4])));
        }
        __syncthreads();
        for (int e = t; e < 648; e += 256) {
            int g = e / 81, kk = e % 81;
            int k = kk / 9, k2 = kk % 9;
            int pk = c_P2[g][k];
            float mb = c_Mbase[pk*9 + k2];
            float v;
            if ((g & 1) == 0) {
                float rr = r_s[g >> 1];
                v = rr * mb + (1.f - rr) * ((k2 == pk) ? 1.f : 0.f);
            } else {
                v = mb;
            }
            g_Mg[e] = v;
        }
    }
}

// ---------------- kernel 4: fused DCN (sample + transform + fp16 MMA GEMM) ----------------
// smem layout (float units), total 16008 floats = 64032 B:
//   U half[32 px][584]   @ 0      (9344 floats)  row = 9 slabs x 64 halves + 8 pad halves
//   A_s [32][9][12]      @ 9344   (3584)   (phase0/1) -- aliased by outb[64][33] in epilogue
//   idx_s[32*9][4] int   @ 12928  (1152)
//   wgt_s[32*9][4]       @ 14080  (1152)
//   wc8T[8][33]          @ 15232  (264)
//   bias_s[512]          @ 15496  (512)
#define USTRH    584
#define A_OFF    9344
#define IDX_OFF  12928
#define WGT_OFF  14080
#define OUTB_OFF 9344
#define WC8_OFF  15232
#define BIAS_OFF 15496
#define SMEM_FLOATS 16008
#define SMEM_BYTES  (SMEM_FLOATS*4)

__global__ __launch_bounds__(256, 3) void main_kernel(
    const float* __restrict__ offset, const float* __restrict__ mask,
    const float* __restrict__ wc8g,   const float* __restrict__ bias,
    float* __restrict__ out)
{
    extern __shared__ float sm[];
    __half* u_h  = (__half*)sm;
    float* A_s   = sm + A_OFF;
    int*   idx_s = (int*)(sm + IDX_OFF);
    float* wgt_s = sm + WGT_OFF;
    float* outb  = sm + OUTB_OFF;
    float* wc8T  = sm + WC8_OFF;
    float* bias_s= sm + BIAS_OFF;

    int t     = threadIdx.x;
    int bid   = blockIdx.x;               // 1024: b(2) * 512 tiles
    int b     = bid >> 9;
    int tbase = (bid & 511) << 5;
    int h     = tbase >> 7;
    int w0    = tbase & 127;
    int w     = t >> 5;
    int l     = t & 31;

    // ---- phase 0a: wc8 (transposed), bias staging ----
    wc8T[w*33 + l] = wc8g[((b*8 + w) << 14) + tbase + l];
    bias_s[t]       = bias[t];
    bias_s[t + 256] = bias[t + 256];

    // ---- phase 0b: bilinear indices & weights (mask folded) ----
    for (int task = t; task < 288; task += 256) {
        int p = task & 31, k = task >> 5;
        int pix = tbase + p;
        float offy = offset[((b*18 + 2*k    ) << 14) + pix];
        float offx = offset[((b*18 + 2*k + 1) << 14) + pix];
        float mval = mask  [((b*9  + k      ) << 14) + pix];
        float py = (float)h        + (float)(k/3) - 1.f + offy;
        float px = (float)(w0 + p) + (float)(k%3) - 1.f + offx;
        float y0f = floorf(py), x0f = floorf(px);
        float ly = py - y0f, lx = px - x0f;
        int y0 = (int)y0f, x0i = (int)x0f;
        int y1 = y0 + 1, x1 = x0i + 1;
        bool vy0 = (y0 >= 0) & (y0 <= 127);
        bool vy1 = (y1 >= 0) & (y1 <= 127);
        bool vx0 = (x0i >= 0) & (x0i <= 127);
        bool vx1 = (x1 >= 0) & (x1 <= 127);
        float w00 = (1.f-ly)*(1.f-lx) * ((vy0 & vx0) ? mval : 0.f);
        float w01 = (1.f-ly)*lx       * ((vy0 & vx1) ? mval : 0.f);
        float w10 = ly*(1.f-lx)       * ((vy1 & vx0) ? mval : 0.f);
        float w11 = ly*lx             * ((vy1 & vx1) ? mval : 0.f);
        int cy0 = min(max(y0, 0), 127), cy1 = min(max(y1, 0), 127);
        int cx0 = min(max(x0i,0), 127), cx1 = min(max(x1, 0), 127);
        int b4 = (p*9 + k)*4;
        idx_s[b4+0] = cy0*128 + cx0;
        idx_s[b4+1] = cy0*128 + cx1;
        idx_s[b4+2] = cy1*128 + cx0;
        idx_s[b4+3] = cy1*128 + cx1;
        wgt_s[b4+0] = w00; wgt_s[b4+1] = w01; wgt_s[b4+2] = w10; wgt_s[b4+3] = w11;
    }
    __syncthreads();

    // ---- phase 0c: A[p][k][k2] = sum_g wc8[g] * M_g ----
    for (int e = t; e < 2592; e += 256) {
        int p = e & 31, kk = e >> 5;
        int k = kk / 9, k2 = kk - k*9;
        float a = 0.f;
        #pragma unroll
        for (int g = 0; g < 8; g++) a += wc8T[g*33 + p] * g_Mg[g*81 + kk];
        A_s[p*112 + k*12 + k2] = a;
    }
    __syncthreads();

    // ---- phase 1: gather + bilinear + tap transform -> u_h (fp16, permuted pos) ----
    {
        const float2* ib = (const float2*)(g_nhwc + ((size_t)b << 20));
        const int4*   idx4 = (const int4*)idx_s;
        const float4* wgt4 = (const float4*)wgt_s;
        // pos of channel 2l within a slab's 64 halves (within=0; 2l+1 is pos+1)
        int pos = (l & 3)*16 + (l >> 3)*4 + ((l >> 2) & 1)*2;
        #pragma unroll
        for (int pp = 0; pp < 4; pp++) {
            int p = w*4 + pp;
            float2 ua[9];
            #pragma unroll
            for (int i = 0; i < 9; i++) { ua[i].x = 0.f; ua[i].y = 0.f; }
            #pragma unroll
            for (int k = 0; k < 9; k++) {
                int4   id = idx4[p*9 + k];
                float4 wg = wgt4[p*9 + k];
                float2 c00 = ib[id.x*32 + l];
                float2 c01 = ib[id.y*32 + l];
                float2 c10 = ib[id.z*32 + l];
                float2 c11 = ib[id.w*32 + l];
                float vx = wg.x*c00.x + wg.y*c01.x + wg.z*c10.x + wg.w*c11.x;
                float vy = wg.x*c00.y + wg.y*c01.y + wg.z*c10.y + wg.w*c11.y;
                const float* Ab = A_s + p*112 + k*12;
                float4 a0 = *(const float4*)(Ab);
                float4 a1 = *(const float4*)(Ab + 4);
                float  a8 = Ab[8];
                ua[0].x += a0.x*vx; ua[0].y += a0.x*vy;
                ua[1].x += a0.y*vx; ua[1].y += a0.y*vy;
                ua[2].x += a0.z*vx; ua[2].y += a0.z*vy;
                ua[3].x += a0.w*vx; ua[3].y += a0.w*vy;
                ua[4].x += a1.x*vx; ua[4].y += a1.x*vy;
                ua[5].x += a1.y*vx; ua[5].y += a1.y*vy;
                ua[6].x += a1.z*vx; ua[6].y += a1.z*vy;
                ua[7].x += a1.w*vx; ua[7].y += a1.w*vy;
                ua[8].x += a8  *vx; ua[8].y += a8  *vy;
            }
            __half* urow = u_h + p*USTRH;
            #pragma unroll
            for (int k2 = 0; k2 < 9; k2++) {
                *(__half2*)(urow + k2*64 + pos) = __floats2half2_rn(ua[k2].x, ua[k2].y);
            }
        }
    }
    __syncthreads();

    // ---- phase 2: fp16 MMA  D[32px x 64o] = u[32 x 576] * W[576 x 64]  (no barriers) ----
    // warp w: px rows m0..m0+15 (m0=(w&1)*16), o cols n0i*16..+15 (n0i=w>>1)
    int m0  = (w & 1) * 16;
    int n0i = w >> 1;
    int g   = l >> 2;
    int tq  = l & 3;
    const __half* uR0 = u_h + (m0 + g)*USTRH + tq*16;
    const __half* uR1 = uR0 + 8*USTRH;
    const __half* Bb  = g_wtf + (n0i*32 + l)*32;

    float acc[2][4];
    #pragma unroll
    for (int j = 0; j < 2; j++)
        #pragma unroll
        for (int i = 0; i < 4; i++) acc[j][i] = 0.f;

    #pragma unroll
    for (int ch = 0; ch < 9; ch++) {
        uint32_t Ag0[8], Ag1[8], Bw[16];
        *(uint4*)(Ag0)     = *(const uint4*)(uR0 + ch*64);
        *(uint4*)(Ag0 + 4) = *(const uint4*)(uR0 + ch*64 + 8);
        *(uint4*)(Ag1)     = *(const uint4*)(uR1 + ch*64);
        *(uint4*)(Ag1 + 4) = *(const uint4*)(uR1 + ch*64 + 8);
        const uint4* Bp = (const uint4*)(Bb + ch*4096);
        *(uint4*)(Bw)      = Bp[0];
        *(uint4*)(Bw + 4)  = Bp[1];
        *(uint4*)(Bw + 8)  = Bp[2];
        *(uint4*)(Bw + 12) = Bp[3];
        #pragma unroll
        for (int s = 0; s < 4; s++) {
            uint32_t a0 = Ag0[s*2], a2 = Ag0[s*2+1];
            uint32_t a1 = Ag1[s*2], a3 = Ag1[s*2+1];
            #pragma unroll
            for (int j = 0; j < 2; j++) {
                uint32_t b0 = Bw[j*8 + s*2], b1 = Bw[j*8 + s*2 + 1];
                asm volatile(
                    "mma.sync.aligned.m16n8k16.row.col.f32.f16.f16.f32 "
                    "{%0,%1,%2,%3}, {%4,%5,%6,%7}, {%8,%9}, {%0,%1,%2,%3};\n"
                    : "+f"(acc[j][0]), "+f"(acc[j][1]), "+f"(acc[j][2]), "+f"(acc[j][3])
                    : "r"(a0), "r"(a1), "r"(a2), "r"(a3), "r"(b0), "r"(b1));
            }
        }
    }

    // ---- epilogue: stage D in smem (outb[o][px]), coalesced NCHW store + bias ----
    __syncthreads();
    #pragma unroll
    for (int j = 0; j < 2; j++) {
        int o = n0i*16 + j*8 + 2*tq;
        outb[(o    )*33 + m0 + g    ] = acc[j][0];
        outb[(o + 1)*33 + m0 + g    ] = acc[j][1];
        outb[(o    )*33 + m0 + g + 8] = acc[j][2];
        outb[(o + 1)*33 + m0 + g + 8] = acc[j][3];
    }
    __syncthreads();
    #pragma unroll
    for (int r = 0; r < 8; r++) {
        int o = r*8 + w;       // constant per warp
        int p = l;
        float be = 0.f;
        #pragma unroll
        for (int gg = 0; gg < 8; gg++) be += wc8T[gg*33 + p] * bias_s[gg*64 + o];
        out[((b*64 + o) << 14) + tbase + p] = outb[o*33 + p] + be;
    }
}

// ---------------- launch ----------------
extern "C" void kernel_launch(void* const* d_in, const int* in_sizes, int n_in,
                              void* d_out, int out_size) {
    const float* input  = (const float*)d_in[0];
    const float* offset = (const float*)d_in[1];
    const float* maskp  = (const float*)d_in[2];
    const float* w_c8   = (const float*)d_in[3];
    const float* weight = (const float*)d_in[4];
    const float* bias   = (const float*)d_in[5];
    const float* fc_w   = (const float*)d_in[6];
    const float* fc_b   = (const float*)d_in[7];
    float* out = (float*)d_out;

    cudaFuncSetAttribute(main_kernel, cudaFuncAttributeMaxDynamicSharedMemorySize, SMEM_BYTES);

    nhwc_kernel   <<<1024, 256>>>(input);
    pool_kernel   <<<128, 256>>>(input);
    wtsetup_kernel<<<145, 256>>>(weight, fc_w, fc_b);
    main_kernel   <<<1024, 256, SMEM_BYTES>>>(offset, maskp, w_c8, bias, out);
}